// round 2
// baseline (speedup 1.0000x reference)
#include <cuda_runtime.h>
#include <cstdint>

// Problem: x [16,128,128,64] fp32 -> A [M=262144, K=64]
//          omega [256,64] fp32   -> B [N=256, K=64] (row-major [N,K] == col-major KxN)
//          out [M, 256, 1] fp32  (trailing singleton is a reshape)
// dist[m,n] = ||x_m||^2 + ||w_n||^2 - 2 * <x_m, w_n>
#define M_TILE 128
#define K_DIM  64
#define N_DIM  256
#define LDA    68          // padded smem row stride (floats) -> conflict-free frag reads
#define NTHREADS 512

__device__ float g_p2[N_DIM];   // ||omega_n||^2 from prologue kernel

// ---------------------------------------------------------------------------
// Prologue: p2[n] = sum_k omega[n][k]^2   (1 CTA, 256 threads)
// ---------------------------------------------------------------------------
__global__ void p2_kernel(const float* __restrict__ omega) {
    int n = threadIdx.x;
    const float4* w = reinterpret_cast<const float4*>(omega + n * K_DIM);
    float s = 0.f;
#pragma unroll
    for (int i = 0; i < K_DIM / 4; i++) {
        float4 v = w[i];
        s += v.x * v.x + v.y * v.y + v.z * v.z + v.w * v.w;
    }
    g_p2[n] = s;
}

// ---------------------------------------------------------------------------
// TF32 helpers
// ---------------------------------------------------------------------------
__device__ __forceinline__ uint32_t f2tf32(float f) {
    uint32_t u;
    asm("cvt.rna.tf32.f32 %0, %1;" : "=r"(u) : "f"(f));
    return u;
}

__device__ __forceinline__ void mma_tf32(float* d, const uint32_t* a,
                                         uint32_t b0, uint32_t b1) {
    asm volatile(
        "mma.sync.aligned.m16n8k8.row.col.f32.tf32.tf32.f32 "
        "{%0,%1,%2,%3}, {%4,%5,%6,%7}, {%8,%9}, {%0,%1,%2,%3};"
        : "+f"(d[0]), "+f"(d[1]), "+f"(d[2]), "+f"(d[3])
        : "r"(a[0]), "r"(a[1]), "r"(a[2]), "r"(a[3]), "r"(b0), "r"(b1));
}

__device__ __forceinline__ void stg_cs_f2(float* p, float x, float y) {
    asm volatile("st.global.cs.v2.f32 [%0], {%1, %2};"
                 :: "l"(p), "f"(x), "f"(y) : "memory");
}

// ---------------------------------------------------------------------------
// Main kernel: one CTA computes a [128 x 256] output tile.
// 512 threads = 16 warps as 4(m) x 4(n); warp tile 32m x 64n
// = 2 m-frags(16) x 8 n-frags(8); K fully unrolled (8 steps of 8).
// A is staged in smem PRE-CONVERTED to tf32 bits (consumed only by MMA + x2).
// ---------------------------------------------------------------------------
__global__ void __launch_bounds__(NTHREADS)
dist_kernel(const float* __restrict__ x,
            const float* __restrict__ omega,
            float* __restrict__ out) {
    __shared__ uint32_t sA[M_TILE * LDA];   // tf32 bit patterns
    __shared__ float sx2[M_TILE];
    __shared__ float sp2[N_DIM];

    const int tid = threadIdx.x;
    const long long m0 = (long long)blockIdx.x * M_TILE;

    // ---- Stage A tile (coalesced float4), converting to tf32 ----
    const float4* gx = reinterpret_cast<const float4*>(x + m0 * K_DIM);
#pragma unroll
    for (int i = tid; i < M_TILE * K_DIM / 4; i += NTHREADS) {
        int row = i >> 4;      // 16 float4 per row
        int c4  = i & 15;
        float4 v = gx[i];
        uint4 t;
        t.x = f2tf32(v.x); t.y = f2tf32(v.y);
        t.z = f2tf32(v.z); t.w = f2tf32(v.w);
        *reinterpret_cast<uint4*>(&sA[row * LDA + c4 * 4]) = t;
    }
    if (tid < N_DIM) sp2[tid] = g_p2[tid];
    __syncthreads();

    // ---- x2 per row from tf32-rounded values (error ~5e-5 rel, fine) ----
    if (tid < M_TILE) {
        const uint32_t* r = &sA[tid * LDA];
        float s = 0.f;
#pragma unroll
        for (int k = 0; k < K_DIM; k++) {
            float v = __uint_as_float(r[k]);
            s += v * v;
        }
        sx2[tid] = s;
    }
    __syncthreads();

    // ---- warp tiling ----
    const int warp = tid >> 5;
    const int lane = tid & 31;
    const int wm = warp >> 2;          // 0..3
    const int wn = warp & 3;           // 0..3
    const int mbase = wm * 32;
    const int nbase = wn * 64;
    const int lr = lane >> 2;          // 0..7
    const int lc = lane & 3;           // 0..3

    float acc[2][8][4];
#pragma unroll
    for (int mt = 0; mt < 2; mt++)
#pragma unroll
        for (int nt = 0; nt < 8; nt++)
#pragma unroll
            for (int i = 0; i < 4; i++) acc[mt][nt][i] = 0.f;

    // ---- main MMA loop over K (8 steps of 8) ----
#pragma unroll
    for (int ks = 0; ks < 8; ks++) {
        const int k0 = ks * 8;
        uint32_t a[2][4];
#pragma unroll
        for (int mt = 0; mt < 2; mt++) {
            const int r0 = mbase + mt * 16 + lr;
            a[mt][0] = sA[r0 * LDA + k0 + lc];
            a[mt][1] = sA[(r0 + 8) * LDA + k0 + lc];
            a[mt][2] = sA[r0 * LDA + k0 + lc + 4];
            a[mt][3] = sA[(r0 + 8) * LDA + k0 + lc + 4];
        }
#pragma unroll
        for (int nt = 0; nt < 8; nt++) {
            const int n = nbase + nt * 8 + lr;
            // omega [N,K] row-major == exact col-major B layout, ldb=64
            uint32_t b0 = f2tf32(__ldg(&omega[n * K_DIM + k0 + lc]));
            uint32_t b1 = f2tf32(__ldg(&omega[n * K_DIM + k0 + lc + 4]));
            mma_tf32(acc[0][nt], a[0], b0, b1);
            mma_tf32(acc[1][nt], a[1], b0, b1);
        }
    }

    // ---- epilogue: dist = x2[m] + p2[n] - 2*xp, streaming stores ----
#pragma unroll
    for (int mt = 0; mt < 2; mt++) {
        const int r0 = mbase + mt * 16 + lr;
        const float xr0 = sx2[r0];
        const float xr1 = sx2[r0 + 8];
        float* o0 = out + (m0 + r0) * N_DIM;
        float* o1 = out + (m0 + r0 + 8) * N_DIM;
#pragma unroll
        for (int nt = 0; nt < 8; nt++) {
            const int col = nbase + nt * 8 + 2 * lc;
            const float p0 = sp2[col];
            const float p1 = sp2[col + 1];
            stg_cs_f2(o0 + col, xr0 + p0 - 2.f * acc[mt][nt][0],
                                xr0 + p1 - 2.f * acc[mt][nt][1]);
            stg_cs_f2(o1 + col, xr1 + p0 - 2.f * acc[mt][nt][2],
                                xr1 + p1 - 2.f * acc[mt][nt][3]);
        }
    }
}

// ---------------------------------------------------------------------------
// Launch
// ---------------------------------------------------------------------------
extern "C" void kernel_launch(void* const* d_in, const int* in_sizes, int n_in,
                              void* d_out, int out_size) {
    const float* p0 = (const float*)d_in[0];
    const float* p1 = (const float*)d_in[1];
    // x is the big tensor (16777216 elems), omega is 16384.
    const float* x     = p0;
    const float* omega = p1;
    if (n_in >= 2 && in_sizes[0] < in_sizes[1]) { x = p1; omega = p0; }

    p2_kernel<<<1, N_DIM>>>(omega);
    const int m_tiles = (16 * 128 * 128) / M_TILE;   // 2048
    dist_kernel<<<m_tiles, NTHREADS>>>(x, omega, (float*)d_out);
}

// round 6
// speedup vs baseline: 1.7303x; 1.7303x over previous
#include <cuda_runtime.h>
#include <cstdint>

// dist[m,n] = ||x_m||^2 + ||w_n||^2 - 2<x_m,w_n>
// x [M=262144, K=64] fp32, omega [N=256, K=64] fp32, out [M,256,1] fp32.
// Ampere-path TF32 mma.sync (proven @198.5us), with B moved to smem (tf32),
// shuffle-reduced x2/p2, single launch. Target: kill the L1 wavefront storm.
#define M_TILE 128
#define K_DIM  64
#define N_DIM  256
#define LDA    68      // padded float stride: bank=(4*row+col)%32 -> conflict-free frags
#define LDB    68
#define NTHREADS 512
#define NTILES 2048

// dynamic smem layout (in floats)
#define F_SB   0                       // 256*68 = 17408
#define F_SA   17408                   // 128*68 = 8704
#define F_P2   26112                   // 256
#define F_X2   26368                   // 128
#define SMEM_FLOATS 26496
#define SMEM_BYTES  (SMEM_FLOATS * 4)  // 105984

// ---------------------------------------------------------------------------
__device__ __forceinline__ uint32_t f2tf32(float f) {
    uint32_t u;
    asm("cvt.rna.tf32.f32 %0, %1;" : "=r"(u) : "f"(f));
    return u;
}

__device__ __forceinline__ void mma_tf32(float* d, const uint32_t* a,
                                         uint32_t b0, uint32_t b1) {
    asm volatile(
        "mma.sync.aligned.m16n8k8.row.col.f32.tf32.tf32.f32 "
        "{%0,%1,%2,%3}, {%4,%5,%6,%7}, {%8,%9}, {%0,%1,%2,%3};"
        : "+f"(d[0]), "+f"(d[1]), "+f"(d[2]), "+f"(d[3])
        : "r"(a[0]), "r"(a[1]), "r"(a[2]), "r"(a[3]), "r"(b0), "r"(b1));
}

__device__ __forceinline__ void stg_cs_f2(float* p, float x, float y) {
    asm volatile("st.global.cs.v2.f32 [%0], {%1, %2};"
                 :: "l"(p), "f"(x), "f"(y) : "memory");
}

// 16-lane sum reduction (groups of 16 within a warp)
__device__ __forceinline__ float red16(float s) {
    s += __shfl_xor_sync(0xffffffffu, s, 8);
    s += __shfl_xor_sync(0xffffffffu, s, 4);
    s += __shfl_xor_sync(0xffffffffu, s, 2);
    s += __shfl_xor_sync(0xffffffffu, s, 1);
    return s;
}

// ---------------------------------------------------------------------------
// One CTA = one [128 x 256] output tile. 16 warps as 4(m) x 4(n);
// warp tile 32m x 64n = 2 m-frags x 8 n-frags; K unrolled (8 steps of 8).
// A and B both live in smem pre-converted to tf32, conflict-free strides.
// ---------------------------------------------------------------------------
__global__ void __launch_bounds__(NTHREADS)
dist_kernel(const float* __restrict__ x,
            const float* __restrict__ omega,
            float* __restrict__ out) {
    extern __shared__ float sm[];
    uint32_t* sBu = (uint32_t*)(sm + F_SB);
    uint32_t* sAu = (uint32_t*)(sm + F_SA);
    float*    sp2 = sm + F_P2;
    float*    sx2 = sm + F_X2;

    const int tid = threadIdx.x;
    const long long m0 = (long long)blockIdx.x * M_TILE;

    // ---- stage B (omega -> smem tf32) + p2 via shuffle reduce ----
    {
        const float4* gw = (const float4*)omega;
#pragma unroll
        for (int j = 0; j < 8; j++) {
            int i = tid + NTHREADS * j;          // 0..4095 (= 256 rows * 16 quads)
            int n = i >> 4, c4 = i & 15;
            float4 v = __ldg(gw + i);
            float ss = red16(v.x * v.x + v.y * v.y + v.z * v.z + v.w * v.w);
            if ((tid & 15) == 0) sp2[n] = ss;
            uint4 t;
            t.x = f2tf32(v.x); t.y = f2tf32(v.y);
            t.z = f2tf32(v.z); t.w = f2tf32(v.w);
            *(uint4*)&sBu[n * LDB + c4 * 4] = t;
        }
    }

    // ---- stage A (x tile -> smem tf32) + x2 via shuffle reduce ----
    {
        const float4* gx = (const float4*)(x + m0 * K_DIM);
#pragma unroll
        for (int j = 0; j < 4; j++) {
            int i = tid + NTHREADS * j;          // 0..2047 (= 128 rows * 16 quads)
            int row = i >> 4, c4 = i & 15;
            float4 v = __ldg(gx + i);
            float ss = red16(v.x * v.x + v.y * v.y + v.z * v.z + v.w * v.w);
            if ((tid & 15) == 0) sx2[row] = ss;
            uint4 t;
            t.x = f2tf32(v.x); t.y = f2tf32(v.y);
            t.z = f2tf32(v.z); t.w = f2tf32(v.w);
            *(uint4*)&sAu[row * LDA + c4 * 4] = t;
        }
    }
    __syncthreads();

    // ---- warp tiling ----
    const int warp = tid >> 5;
    const int lane = tid & 31;
    const int wm = warp >> 2;          // 0..3
    const int wn = warp & 3;           // 0..3
    const int mbase = wm * 32;
    const int nbase = wn * 64;
    const int lr = lane >> 2;          // 0..7
    const int lc = lane & 3;           // 0..3

    float acc[2][8][4];
#pragma unroll
    for (int mt = 0; mt < 2; mt++)
#pragma unroll
        for (int nt = 0; nt < 8; nt++)
#pragma unroll
            for (int i = 0; i < 4; i++) acc[mt][nt][i] = 0.f;

    // ---- main MMA loop: K in 8 steps of 8; all operands from smem ----
#pragma unroll
    for (int ks = 0; ks < 8; ks++) {
        const int k0 = ks * 8;
        uint32_t a[2][4];
#pragma unroll
        for (int mt = 0; mt < 2; mt++) {
            const int r0 = mbase + mt * 16 + lr;
            a[mt][0] = sAu[r0 * LDA + k0 + lc];
            a[mt][1] = sAu[(r0 + 8) * LDA + k0 + lc];
            a[mt][2] = sAu[r0 * LDA + k0 + lc + 4];
            a[mt][3] = sAu[(r0 + 8) * LDA + k0 + lc + 4];
        }
#pragma unroll
        for (int nt = 0; nt < 8; nt++) {
            const int n = nbase + nt * 8 + lr;
            uint32_t b0 = sBu[n * LDB + k0 + lc];       // bank (4n+k0+lc)%32: all distinct
            uint32_t b1 = sBu[n * LDB + k0 + lc + 4];
            mma_tf32(acc[0][nt], a[0], b0, b1);
            mma_tf32(acc[1][nt], a[1], b0, b1);
        }
    }

    // ---- epilogue: dist = x2[m] + p2[n] - 2*xp, streaming v2 stores ----
#pragma unroll
    for (int mt = 0; mt < 2; mt++) {
        const int r0 = mbase + mt * 16 + lr;
        const float xr0 = sx2[r0];
        const float xr1 = sx2[r0 + 8];
        float* o0 = out + (m0 + r0) * N_DIM;
        float* o1 = out + (m0 + r0 + 8) * N_DIM;
#pragma unroll
        for (int nt = 0; nt < 8; nt++) {
            const int col = nbase + nt * 8 + 2 * lc;
            const float p0 = sp2[col];
            const float p1 = sp2[col + 1];
            stg_cs_f2(o0 + col, xr0 + p0 - 2.f * acc[mt][nt][0],
                                xr0 + p1 - 2.f * acc[mt][nt][1]);
            stg_cs_f2(o1 + col, xr1 + p0 - 2.f * acc[mt][nt][2],
                                xr1 + p1 - 2.f * acc[mt][nt][3]);
        }
    }
}

// ---------------------------------------------------------------------------
extern "C" void kernel_launch(void* const* d_in, const int* in_sizes, int n_in,
                              void* d_out, int out_size) {
    const float* p0 = (const float*)d_in[0];
    const float* p1 = (const float*)d_in[1];
    // x is the big tensor (16777216 elems), omega is 16384.
    const float* x = p0, *omega = p1;
    if (n_in >= 2 && in_sizes[0] < in_sizes[1]) { x = p1; omega = p0; }

    (void)cudaFuncSetAttribute(dist_kernel,
                               cudaFuncAttributeMaxDynamicSharedMemorySize,
                               SMEM_BYTES);
    dist_kernel<<<NTILES, NTHREADS, SMEM_BYTES>>>(x, omega, (float*)d_out);
}

// round 8
// speedup vs baseline: 2.1523x; 1.2439x over previous
#include <cuda_runtime.h>
#include <cstdint>

// dist[m,n] = ||x_m||^2 + ||w_n||^2 - 2<x_m,w_n>
// x [M=262144, K=64] fp32, omega [N=256, K=64] fp32, out [M,256,1] fp32.
// TF32 mma.sync, PERSISTENT CTAs: B staged once, A double-buffered with
// register prefetch, one sync per tile -> phases pipeline across warps.
// (Identical to R7 design; kernel_launch hardened: no runtime attribute
//  queries, grid hardcoded to 148 SMs.)
#define M_TILE 128
#define K_DIM  64
#define N_DIM  256
#define LDA    68      // padded float stride: bank=(4*row+col)%32 -> conflict-free
#define LDB    68
#define NTHREADS 512
#define NTILES 2048
#define GRID_SMS 148   // sm_100a B200

// dynamic smem layout (in floats)
#define F_SB   0                        // 256*68 = 17408
#define F_SA   17408                    // 2 bufs x 128*68 = 17408
#define F_P2   34816                    // 256
#define F_X2   35072                    // 2 x 128
#define SMEM_FLOATS 35328
#define SMEM_BYTES  (SMEM_FLOATS * 4)   // 141312

// ---------------------------------------------------------------------------
__device__ __forceinline__ uint32_t f2tf32(float f) {
    uint32_t u;
    asm("cvt.rna.tf32.f32 %0, %1;" : "=r"(u) : "f"(f));
    return u;
}

__device__ __forceinline__ void mma_tf32(float* d, const uint32_t* a,
                                         uint32_t b0, uint32_t b1) {
    asm volatile(
        "mma.sync.aligned.m16n8k8.row.col.f32.tf32.tf32.f32 "
        "{%0,%1,%2,%3}, {%4,%5,%6,%7}, {%8,%9}, {%0,%1,%2,%3};"
        : "+f"(d[0]), "+f"(d[1]), "+f"(d[2]), "+f"(d[3])
        : "r"(a[0]), "r"(a[1]), "r"(a[2]), "r"(a[3]), "r"(b0), "r"(b1));
}

__device__ __forceinline__ void stg_cs_f2(float* p, float x, float y) {
    asm volatile("st.global.cs.v2.f32 [%0], {%1, %2};"
                 :: "l"(p), "f"(x), "f"(y) : "memory");
}

__device__ __forceinline__ float red16(float s) {
    s += __shfl_xor_sync(0xffffffffu, s, 8);
    s += __shfl_xor_sync(0xffffffffu, s, 4);
    s += __shfl_xor_sync(0xffffffffu, s, 2);
    s += __shfl_xor_sync(0xffffffffu, s, 1);
    return s;
}

// ---------------------------------------------------------------------------
// Persistent CTA: loops over [128 x 256] output tiles.
// 16 warps as 4(m) x 4(n); warp tile 32m x 64n; K unrolled (8 steps of 8).
// ---------------------------------------------------------------------------
__global__ void __launch_bounds__(NTHREADS, 1)
dist_kernel(const float* __restrict__ x,
            const float* __restrict__ omega,
            float* __restrict__ out) {
    extern __shared__ float sm[];
    uint32_t* sBu = (uint32_t*)(sm + F_SB);
    float*    sp2 = sm + F_P2;
    float*    sx2 = sm + F_X2;          // [2][128]

    const int tid = threadIdx.x;
    const int row16 = tid >> 4;         // 0..31 (row within a 512-thread sweep)
    const int c4    = tid & 15;

    // ---- stage B once (omega -> smem tf32) + p2 via shuffle reduce ----
    {
        const float4* gw = (const float4*)omega;
#pragma unroll
        for (int j = 0; j < 8; j++) {
            int i = tid + NTHREADS * j;          // 0..4095 (256 rows * 16 quads)
            int n = i >> 4, cc = i & 15;
            float4 v = __ldg(gw + i);
            float ss = red16(v.x * v.x + v.y * v.y + v.z * v.z + v.w * v.w);
            if ((tid & 15) == 0) sp2[n] = ss;
            uint4 t;
            t.x = f2tf32(v.x); t.y = f2tf32(v.y);
            t.z = f2tf32(v.z); t.w = f2tf32(v.w);
            *(uint4*)&sBu[n * LDB + cc * 4] = t;
        }
    }

    // ---- warp tiling constants ----
    const int warp = tid >> 5;
    const int lane = tid & 31;
    const int wm = warp >> 2;
    const int wn = warp & 3;
    const int mbase = wm * 32;
    const int nbase = wn * 64;
    const int lr = lane >> 2;
    const int lc = lane & 3;

    const int grid = gridDim.x;
    const int bid  = blockIdx.x;

    // ---- prefetch first tile into registers ----
    float4 v[4];
    {
        const float4* gx = (const float4*)(x + (long long)bid * M_TILE * K_DIM);
#pragma unroll
        for (int j = 0; j < 4; j++) v[j] = __ldg(gx + tid + NTHREADS * j);
    }

    int k = 0;
    for (int t = bid; t < NTILES; t += grid, k++) {
        const int b = k & 1;
        uint32_t* sAu = (uint32_t*)(sm + F_SA) + b * (M_TILE * LDA);

        // ---- stage prefetched regs -> smem buf b (+ x2 shuffle reduce) ----
#pragma unroll
        for (int j = 0; j < 4; j++) {
            int row = row16 + 32 * j;
            float4 w = v[j];
            float ss = red16(w.x * w.x + w.y * w.y + w.z * w.z + w.w * w.w);
            if ((tid & 15) == 0) sx2[b * 128 + row] = ss;
            uint4 tv;
            tv.x = f2tf32(w.x); tv.y = f2tf32(w.y);
            tv.z = f2tf32(w.z); tv.w = f2tf32(w.w);
            *(uint4*)&sAu[row * LDA + c4 * 4] = tv;
        }
        __syncthreads();

        // ---- issue prefetch LDGs for next tile (hidden under MMA) ----
        const int tn = t + grid;
        if (tn < NTILES) {
            const float4* gx = (const float4*)(x + (long long)tn * M_TILE * K_DIM);
#pragma unroll
            for (int j = 0; j < 4; j++) v[j] = __ldg(gx + tid + NTHREADS * j);
        }

        // ---- MMA: K in 8 steps of 8, operands from smem ----
        float acc[2][8][4];
#pragma unroll
        for (int mt = 0; mt < 2; mt++)
#pragma unroll
            for (int nt = 0; nt < 8; nt++)
#pragma unroll
                for (int i = 0; i < 4; i++) acc[mt][nt][i] = 0.f;

#pragma unroll
        for (int ks = 0; ks < 8; ks++) {
            const int k0 = ks * 8;
            uint32_t a[2][4];
#pragma unroll
            for (int mt = 0; mt < 2; mt++) {
                const int r0 = mbase + mt * 16 + lr;
                a[mt][0] = sAu[r0 * LDA + k0 + lc];
                a[mt][1] = sAu[(r0 + 8) * LDA + k0 + lc];
                a[mt][2] = sAu[r0 * LDA + k0 + lc + 4];
                a[mt][3] = sAu[(r0 + 8) * LDA + k0 + lc + 4];
            }
#pragma unroll
            for (int nt = 0; nt < 8; nt++) {
                const int n = nbase + nt * 8 + lr;
                uint32_t b0 = sBu[n * LDB + k0 + lc];
                uint32_t b1 = sBu[n * LDB + k0 + lc + 4];
                mma_tf32(acc[0][nt], a[0], b0, b1);
                mma_tf32(acc[1][nt], a[1], b0, b1);
            }
        }

        // ---- epilogue: dist = x2 + p2 - 2*xp, streaming v2 stores ----
        const long long m0 = (long long)t * M_TILE;
#pragma unroll
        for (int mt = 0; mt < 2; mt++) {
            const int r0 = mbase + mt * 16 + lr;
            const float xr0 = sx2[b * 128 + r0];
            const float xr1 = sx2[b * 128 + r0 + 8];
            float* o0 = out + (m0 + r0) * N_DIM;
            float* o1 = out + (m0 + r0 + 8) * N_DIM;
#pragma unroll
            for (int nt = 0; nt < 8; nt++) {
                const int col = nbase + nt * 8 + 2 * lc;
                const float p0 = sp2[col];
                const float p1 = sp2[col + 1];
                stg_cs_f2(o0 + col, xr0 + p0 - 2.f * acc[mt][nt][0],
                                    xr0 + p1 - 2.f * acc[mt][nt][1]);
                stg_cs_f2(o1 + col, xr1 + p0 - 2.f * acc[mt][nt][2],
                                    xr1 + p1 - 2.f * acc[mt][nt][3]);
            }
        }
    }
}

// ---------------------------------------------------------------------------
extern "C" void kernel_launch(void* const* d_in, const int* in_sizes, int n_in,
                              void* d_out, int out_size) {
    const float* p0 = (const float*)d_in[0];
    const float* p1 = (const float*)d_in[1];
    // x is the big tensor (16777216 elems), omega is 16384.
    const float* x = p0, *omega = p1;
    if (n_in >= 2 && in_sizes[0] < in_sizes[1]) { x = p1; omega = p0; }

    (void)cudaFuncSetAttribute(dist_kernel,
                               cudaFuncAttributeMaxDynamicSharedMemorySize,
                               SMEM_BYTES);
    int grid = GRID_SMS < NTILES ? GRID_SMS : NTILES;
    dist_kernel<<<grid, NTHREADS, SMEM_BYTES>>>(x, omega, (float*)d_out);
}